// round 2
// baseline (speedup 1.0000x reference)
#include <cuda_runtime.h>
#include <math_constants.h>
#include <stdint.h>

#define BB 8
#define CC 256
#define TT 2048
#define NN (BB*TT)          // 16384 points
#define KNN 10
#define FULLMASK 0xffffffffu

// ------------------- scratch (static device globals; no allocation) -------
__device__ float g_sq[NN];                       // 64 KB
__device__ float g_G[(size_t)BB*TT*TT];          // 134 MB  dif matrix
__device__ int   g_neigh[NN*KNN];                // 640 KB  global neighbor ids
__device__ float g_Y1[(size_t)NN*CC];            // 16 MB   W1 * feat
__device__ float g_Y2[(size_t)NN*CC];            // 16 MB   W2 * feat
__device__ float g_S [(size_t)NN*CC];            // 16 MB   conv + b_conv + b_mlp

// ===========================================================================
// 1) squared norms  sq[b,t] = sum_c x[b,c,t]^2
// ===========================================================================
__global__ __launch_bounds__(256) void k_sq(const float* __restrict__ x)
{
    int n = blockIdx.x * 256 + threadIdx.x;      // n = b*T + t
    int b = n >> 11;
    int t = n & (TT - 1);
    const float* p = x + (size_t)b * CC * TT + t;
    float s = 0.f;
#pragma unroll 8
    for (int c = 0; c < CC; c++) {
        float v = p[(size_t)c * TT];
        s += v * v;
    }
    g_sq[n] = s;
}

// ===========================================================================
// 2) gram + dif:   G[b,i,j] = sq_i + sq_j - 2 * sum_c x[b,c,i] x[b,c,j]
//    128x128 block tile, 8x8 micro tile, K = 256
// ===========================================================================
__global__ __launch_bounds__(256) void k_gram(const float* __restrict__ x)
{
    __shared__ float As[8][128];
    __shared__ float Bs[8][128];

    const int b  = blockIdx.z;
    const int i0 = blockIdx.y * 128;
    const int j0 = blockIdx.x * 128;
    const int tid = threadIdx.x;
    const int tx = tid & 15;          // j fragment
    const int ty = tid >> 4;          // i fragment
    const float* xb = x + (size_t)b * CC * TT;

    float acc[8][8];
#pragma unroll
    for (int a = 0; a < 8; a++)
#pragma unroll
        for (int c = 0; c < 8; c++) acc[a][c] = 0.f;

    const int lkk  = tid >> 5;        // 0..7
    const int lcol = (tid & 31) * 4;  // 0..124

    for (int kt = 0; kt < CC; kt += 8) {
        float4 av = *(const float4*)(xb + (size_t)(kt + lkk) * TT + i0 + lcol);
        float4 bv = *(const float4*)(xb + (size_t)(kt + lkk) * TT + j0 + lcol);
        __syncthreads();
        *(float4*)&As[lkk][lcol] = av;
        *(float4*)&Bs[lkk][lcol] = bv;
        __syncthreads();
#pragma unroll
        for (int kk = 0; kk < 8; kk++) {
            float a[8], bj[8];
            *(float4*)&a[0]  = *(float4*)&As[kk][4*ty];
            *(float4*)&a[4]  = *(float4*)&As[kk][64 + 4*ty];
            *(float4*)&bj[0] = *(float4*)&Bs[kk][4*tx];
            *(float4*)&bj[4] = *(float4*)&Bs[kk][64 + 4*tx];
#pragma unroll
            for (int ii = 0; ii < 8; ii++)
#pragma unroll
                for (int jj = 0; jj < 8; jj++)
                    acc[ii][jj] += a[ii] * bj[jj];
        }
    }

    // epilogue: dif = sq_i + sq_j - 2*acc
    float sqi[8], sqj[8];
#pragma unroll
    for (int ii = 0; ii < 8; ii++) {
        int il = (ii < 4) ? (4*ty + ii) : (64 + 4*ty + ii - 4);
        sqi[ii] = g_sq[b*TT + i0 + il];
    }
#pragma unroll
    for (int jj = 0; jj < 8; jj++) {
        int jl = (jj < 4) ? (4*tx + jj) : (64 + 4*tx + jj - 4);
        sqj[jj] = g_sq[b*TT + j0 + jl];
    }
#pragma unroll
    for (int ii = 0; ii < 8; ii++) {
        int il = (ii < 4) ? (4*ty + ii) : (64 + 4*ty + ii - 4);
        float* row = g_G + ((size_t)(b*TT + i0 + il)) * TT + j0;
        float4 w0, w1;
        w0.x = sqi[ii] + sqj[0] - 2.f*acc[ii][0];
        w0.y = sqi[ii] + sqj[1] - 2.f*acc[ii][1];
        w0.z = sqi[ii] + sqj[2] - 2.f*acc[ii][2];
        w0.w = sqi[ii] + sqj[3] - 2.f*acc[ii][3];
        w1.x = sqi[ii] + sqj[4] - 2.f*acc[ii][4];
        w1.y = sqi[ii] + sqj[5] - 2.f*acc[ii][5];
        w1.z = sqi[ii] + sqj[6] - 2.f*acc[ii][6];
        w1.w = sqi[ii] + sqj[7] - 2.f*acc[ii][7];
        *(float4*)(row + 4*tx)      = w0;
        *(float4*)(row + 64 + 4*tx) = w1;
    }
}

// ===========================================================================
// 3) dual top-k per row (warp per row).  overall top-10 and "allowed" top-10
// ===========================================================================
__device__ __forceinline__ bool plt(float v1, int i1, float v2, int i2)
{
    return v1 < v2 || (v1 == v2 && i1 < i2);
}

__device__ __forceinline__ void warp_merge10(const float* sv, const int* si,
                                             int lane, float* resv, int* resi)
{
    int pi = 0;
#pragma unroll
    for (int r = 0; r < 10; r++) {
        float bv; int bi;
        if (pi < 10) { bv = sv[lane*10 + pi]; bi = si[lane*10 + pi]; }
        else         { bv = CUDART_INF_F;     bi = 0x7fffffff; }
        int bl = lane;
#pragma unroll
        for (int off = 16; off > 0; off >>= 1) {
            float ov = __shfl_down_sync(FULLMASK, bv, off);
            int   oi = __shfl_down_sync(FULLMASK, bi, off);
            int   ol = __shfl_down_sync(FULLMASK, bl, off);
            if (ov < bv || (ov == bv && oi < bi)) { bv = ov; bi = oi; bl = ol; }
        }
        bv = __shfl_sync(FULLMASK, bv, 0);
        bi = __shfl_sync(FULLMASK, bi, 0);
        bl = __shfl_sync(FULLMASK, bl, 0);
        if (lane == bl) pi++;
        resv[r] = bv; resi[r] = bi;
    }
}

__global__ __launch_bounds__(256) void k_topk(const int* __restrict__ num_frms)
{
    __shared__ float sv[8][320];
    __shared__ int   si[8][320];

    const int wloc = threadIdx.x >> 5;
    const int lane = threadIdx.x & 31;
    const int row  = blockIdx.x * 8 + wloc;         // row = b*T + i
    const int b = row >> 11;
    const int i = row & (TT - 1);

    const int nf  = num_frms[b];
    const int thr = nf + 20;                         // ratio == 1
    const bool condb = (nf <= 819);                  // nf <= 0.4*2048
    const bool irow  = (i >= thr);

    const float* rp = g_G + (size_t)row * TT;

    float ov[10]; int oi[10];        // overall top-10 (ascending)
    float av[10]; int ai[10];        // allowed top-10
#pragma unroll
    for (int q = 0; q < 10; q++) {
        ov[q] = CUDART_INF_F; oi[q] = 0x7fffffff;
        av[q] = CUDART_INF_F; ai[q] = 0x7fffffff;
    }

    for (int m = 0; m < 64; m++) {
        int j = lane + (m << 5);
        float v = rp[j];
        if (plt(v, j, ov[9], oi[9])) {
            ov[9] = v; oi[9] = j;
#pragma unroll
            for (int q = 9; q > 0; q--) {
                if (plt(ov[q], oi[q], ov[q-1], oi[q-1])) {
                    float tv = ov[q]; ov[q] = ov[q-1]; ov[q-1] = tv;
                    int   ti = oi[q]; oi[q] = oi[q-1]; oi[q-1] = ti;
                }
            }
        }
        if (!(irow && j >= thr)) {
            if (plt(v, j, av[9], ai[9])) {
                av[9] = v; ai[9] = j;
#pragma unroll
                for (int q = 9; q > 0; q--) {
                    if (plt(av[q], ai[q], av[q-1], ai[q-1])) {
                        float tv = av[q]; av[q] = av[q-1]; av[q-1] = tv;
                        int   ti = ai[q]; ai[q] = ai[q-1]; ai[q-1] = ti;
                    }
                }
            }
        }
    }

    float resov[10]; int resoi[10];
    float resav[10]; int resai[10];

    // merge overall
#pragma unroll
    for (int q = 0; q < 10; q++) { sv[wloc][lane*10+q] = ov[q]; si[wloc][lane*10+q] = oi[q]; }
    __syncwarp();
    warp_merge10(sv[wloc], si[wloc], lane, resov, resoi);
    __syncwarp();
    // merge allowed
#pragma unroll
    for (int q = 0; q < 10; q++) { sv[wloc][lane*10+q] = av[q]; si[wloc][lane*10+q] = ai[q]; }
    __syncwarp();
    warp_merge10(sv[wloc], si[wloc], lane, resav, resai);

    if (lane == 0) {
        int outI[10];
#pragma unroll
        for (int q = 0; q < 5; q++) outI[q] = resoi[q];
        if (condb) {
            int cnt = 5;
#pragma unroll
            for (int q = 0; q < 10; q++) {
                int c = resai[q];
                bool dup = (c == outI[0]) | (c == outI[1]) | (c == outI[2]) |
                           (c == outI[3]) | (c == outI[4]);
                if (!dup && cnt < 10) { outI[cnt] = c; cnt++; }
            }
        } else {
#pragma unroll
            for (int q = 5; q < 10; q++) outI[q] = resoi[q];
        }
#pragma unroll
        for (int k = 0; k < KNN; k++)
            g_neigh[row * KNN + k] = b * TT + outI[k];
    }
}

// ===========================================================================
// 4) Y1 = W1 * feat, Y2 = W2 * feat   (W1 = W_mlp[:, :256], W2 = W_mlp[:, 256:])
//    tile: 128 o x 64 t, micro 8o x 4t
// ===========================================================================
__global__ __launch_bounds__(256) void k_mlp(const float* __restrict__ x,
                                             const float* __restrict__ Wm)
{
    __shared__ float xs[16][64];
    __shared__ float w1s[16][128];
    __shared__ float w2s[16][128];

    const int b  = blockIdx.z;
    const int t0 = blockIdx.x * 64;
    const int o0 = blockIdx.y * 128;
    const int tid = threadIdx.x;
    const int tx = tid & 15;        // o fragment
    const int ty = tid >> 4;        // t fragment
    const float* xb = x + (size_t)b * CC * TT;

    float a1[4][8], a2[4][8];
#pragma unroll
    for (int ti = 0; ti < 4; ti++)
#pragma unroll
        for (int oi = 0; oi < 8; oi++) { a1[ti][oi] = 0.f; a2[ti][oi] = 0.f; }

    for (int kt = 0; kt < CC; kt += 16) {
        float4 xv = *(const float4*)(xb + (size_t)(kt + (tid >> 4)) * TT + t0 + (tid & 15) * 4);
        int lin0 = tid, lin1 = tid + 256;
        int ol0 = lin0 & 127, kg0 = lin0 >> 7;
        int ol1 = lin1 & 127, kg1 = lin1 >> 7;
        float4 w1v0 = *(const float4*)(Wm + (size_t)(o0 + ol0) * 512 + kt + kg0 * 4);
        float4 w2v0 = *(const float4*)(Wm + (size_t)(o0 + ol0) * 512 + 256 + kt + kg0 * 4);
        float4 w1v1 = *(const float4*)(Wm + (size_t)(o0 + ol1) * 512 + kt + kg1 * 4);
        float4 w2v1 = *(const float4*)(Wm + (size_t)(o0 + ol1) * 512 + 256 + kt + kg1 * 4);
        __syncthreads();
        *(float4*)&xs[tid >> 4][(tid & 15) * 4] = xv;
        {
            int kk = kg0 * 4;
            w1s[kk][ol0]=w1v0.x; w1s[kk+1][ol0]=w1v0.y; w1s[kk+2][ol0]=w1v0.z; w1s[kk+3][ol0]=w1v0.w;
            w2s[kk][ol0]=w2v0.x; w2s[kk+1][ol0]=w2v0.y; w2s[kk+2][ol0]=w2v0.z; w2s[kk+3][ol0]=w2v0.w;
        }
        {
            int kk = kg1 * 4;
            w1s[kk][ol1]=w1v1.x; w1s[kk+1][ol1]=w1v1.y; w1s[kk+2][ol1]=w1v1.z; w1s[kk+3][ol1]=w1v1.w;
            w2s[kk][ol1]=w2v1.x; w2s[kk+1][ol1]=w2v1.y; w2s[kk+2][ol1]=w2v1.z; w2s[kk+3][ol1]=w2v1.w;
        }
        __syncthreads();
#pragma unroll
        for (int kk = 0; kk < 16; kk++) {
            float xr[4];
            *(float4*)xr = *(float4*)&xs[kk][4*ty];
            float w1r[8], w2r[8];
            *(float4*)&w1r[0] = *(float4*)&w1s[kk][4*tx];
            *(float4*)&w1r[4] = *(float4*)&w1s[kk][64 + 4*tx];
            *(float4*)&w2r[0] = *(float4*)&w2s[kk][4*tx];
            *(float4*)&w2r[4] = *(float4*)&w2s[kk][64 + 4*tx];
#pragma unroll
            for (int ti = 0; ti < 4; ti++)
#pragma unroll
                for (int oi = 0; oi < 8; oi++) {
                    a1[ti][oi] += xr[ti] * w1r[oi];
                    a2[ti][oi] += xr[ti] * w2r[oi];
                }
        }
    }

#pragma unroll
    for (int ti = 0; ti < 4; ti++) {
        size_t base = (size_t)(b*TT + t0 + 4*ty + ti) * CC + o0;
        *(float4*)(g_Y1 + base + 4*tx)      = make_float4(a1[ti][0], a1[ti][1], a1[ti][2], a1[ti][3]);
        *(float4*)(g_Y1 + base + 64 + 4*tx) = make_float4(a1[ti][4], a1[ti][5], a1[ti][6], a1[ti][7]);
        *(float4*)(g_Y2 + base + 4*tx)      = make_float4(a2[ti][0], a2[ti][1], a2[ti][2], a2[ti][3]);
        *(float4*)(g_Y2 + base + 64 + 4*tx) = make_float4(a2[ti][4], a2[ti][5], a2[ti][6], a2[ti][7]);
    }
}

// ===========================================================================
// 5) conv1d (k=3, pad 1) as 3 shifted GEMMs; writes S = conv + b_conv + b_mlp
// ===========================================================================
__global__ __launch_bounds__(256) void k_conv(const float* __restrict__ x,
                                              const float* __restrict__ Wc,
                                              const float* __restrict__ bc,
                                              const float* __restrict__ bm)
{
    __shared__ float xs[16][68];          // 66 used (halo), padded
    __shared__ float wcs[3][16][128];

    const int b  = blockIdx.z;
    const int t0 = blockIdx.x * 64;
    const int o0 = blockIdx.y * 128;
    const int tid = threadIdx.x;
    const int tx = tid & 15;        // o fragment
    const int ty = tid >> 4;        // t fragment
    const float* xb = x + (size_t)b * CC * TT;

    float ac[4][8];
#pragma unroll
    for (int ti = 0; ti < 4; ti++)
#pragma unroll
        for (int oi = 0; oi < 8; oi++) ac[ti][oi] = 0.f;

    for (int kt = 0; kt < CC; kt += 16) {
        __syncthreads();
        for (int idx = tid; idx < 16 * 66; idx += 256) {
            int kk = idx / 66, u = idx - kk * 66;
            int gt = t0 - 1 + u;
            float v = (gt >= 0 && gt < TT) ? xb[(size_t)(kt + kk) * TT + gt] : 0.f;
            xs[kk][u] = v;
        }
        for (int idx = tid; idx < 3 * 16 * 128; idx += 256) {
            int ol = idx & 127;
            int kk = (idx >> 7) & 15;
            int s  = idx >> 11;
            wcs[s][kk][ol] = Wc[(size_t)(o0 + ol) * 768 + (kt + kk) * 3 + s];
        }
        __syncthreads();
#pragma unroll
        for (int kk = 0; kk < 16; kk++) {
            float xr[6];
#pragma unroll
            for (int u = 0; u < 6; u++) xr[u] = xs[kk][4*ty + u];
#pragma unroll
            for (int s = 0; s < 3; s++) {
                float w[8];
                *(float4*)&w[0] = *(float4*)&wcs[s][kk][4*tx];
                *(float4*)&w[4] = *(float4*)&wcs[s][kk][64 + 4*tx];
#pragma unroll
                for (int ti = 0; ti < 4; ti++)
#pragma unroll
                    for (int oi = 0; oi < 8; oi++)
                        ac[ti][oi] += xr[ti + s] * w[oi];
            }
        }
    }

    float bias[8];
#pragma unroll
    for (int oi = 0; oi < 8; oi++) {
        int o = o0 + ((oi < 4) ? (4*tx + oi) : (64 + 4*tx + oi - 4));
        bias[oi] = bc[o] + bm[o];
    }
#pragma unroll
    for (int ti = 0; ti < 4; ti++) {
        size_t base = (size_t)(b*TT + t0 + 4*ty + ti) * CC + o0;
        *(float4*)(g_S + base + 4*tx)      = make_float4(ac[ti][0]+bias[0], ac[ti][1]+bias[1],
                                                         ac[ti][2]+bias[2], ac[ti][3]+bias[3]);
        *(float4*)(g_S + base + 64 + 4*tx) = make_float4(ac[ti][4]+bias[4], ac[ti][5]+bias[5],
                                                         ac[ti][6]+bias[6], ac[ti][7]+bias[7]);
    }
}

// ===========================================================================
// 6) final: out[b,o,t2] = relu(max over pooled pair of (S + Y2 + max_k Y1[nbr]))
// ===========================================================================
__global__ __launch_bounds__(256) void k_final(float* __restrict__ out)
{
    __shared__ float rt[256][33];
    __shared__ int   nb[80];

    const int gx = blockIdx.x;     // t2 group of 32
    const int b  = blockIdx.y;
    const int tid = threadIdx.x;   // = o
    const int t2base = gx * 32;

    for (int sub = 0; sub < 8; sub++) {
        __syncthreads();
        int nbase = b * TT + (t2base + sub * 4) * 2;    // 8 points
        if (tid < 80) nb[tid] = g_neigh[(size_t)nbase * KNN + tid];
        __syncthreads();
        int o = tid;
#pragma unroll
        for (int t2l = 0; t2l < 4; t2l++) {
            int p0 = t2l * 2, p1 = p0 + 1;
            float m0 = -CUDART_INF_F, m1 = -CUDART_INF_F;
#pragma unroll
            for (int k = 0; k < KNN; k++) {
                m0 = fmaxf(m0, g_Y1[(size_t)nb[p0*KNN + k] * CC + o]);
                m1 = fmaxf(m1, g_Y1[(size_t)nb[p1*KNN + k] * CC + o]);
            }
            int n0 = nbase + p0, n1 = nbase + p1;
            float v0 = g_S[(size_t)n0*CC + o] + g_Y2[(size_t)n0*CC + o] + m0;
            float v1 = g_S[(size_t)n1*CC + o] + g_Y2[(size_t)n1*CC + o] + m1;
            rt[o][sub*4 + t2l] = fmaxf(fmaxf(v0, v1), 0.f);
        }
    }
    __syncthreads();
    float* ob = out + (size_t)b * CC * (TT/2) + t2base;
    for (int w = 0; w < 32; w++) {
        int lin = w * 256 + tid;
        int o = lin >> 5, c = lin & 31;
        ob[(size_t)o * (TT/2) + c] = rt[o][c];
    }
}

// ===========================================================================
extern "C" void kernel_launch(void* const* d_in, const int* in_sizes, int n_in,
                              void* d_out, int out_size)
{
    const float* x   = (const float*)d_in[0];
    const int*   nfr = (const int*)  d_in[1];
    const float* Wc  = (const float*)d_in[2];
    const float* bc  = (const float*)d_in[3];
    const float* Wm  = (const float*)d_in[4];
    const float* bm  = (const float*)d_in[5];
    float* out = (float*)d_out;

    k_sq  <<<NN/256, 256>>>(x);
    k_gram<<<dim3(16,16,BB), 256>>>(x);
    k_topk<<<NN/8, 256>>>(nfr);
    k_mlp <<<dim3(32,2,BB), 256>>>(x, Wm);
    k_conv<<<dim3(32,2,BB), 256>>>(x, Wc, bc, bm);
    k_final<<<dim3(32,BB), 256>>>(out);
}

// round 10
// speedup vs baseline: 1.0496x; 1.0496x over previous
#include <cuda_runtime.h>
#include <cuda_bf16.h>
#include <math_constants.h>
#include <stdint.h>

#define BB 8
#define CC 256
#define TT 2048
#define NN (BB*TT)          // 16384 points
#define KNN 10
#define FULLMASK 0xffffffffu

// ------------------- scratch (static device globals; no allocation) -------
__device__ float g_sq[NN];                        // 64 KB
__device__ int   g_neigh[NN*KNN];                 // 640 KB
__device__ float g_Y1[(size_t)NN*CC];             // 16 MB
__device__ float g_Y2[(size_t)NN*CC];             // 16 MB
__device__ float g_S [(size_t)NN*CC];             // 16 MB
// x transposed, bf16 hi/lo concatenated along K: [b][t][0:256]=hi, [256:512]=lo
__device__ __nv_bfloat16 g_xT[(size_t)NN*512];    // 16 MB

__device__ __forceinline__ uint32_t smem_u32(const void* p) {
    uint32_t a;
    asm("{ .reg .u64 tmp; cvta.to.shared.u64 tmp, %1; cvt.u32.u64 %0, tmp; }"
        : "=r"(a) : "l"(p));
    return a;
}

// ===========================================================================
// 0) convert x -> transposed bf16 hi/lo  g_xT[b][t][512]
// ===========================================================================
__global__ __launch_bounds__(256) void k_cvt(const float* __restrict__ x)
{
    __shared__ float s[32][33];
    const int t0 = blockIdx.x * 32, c0 = blockIdx.y * 32, b = blockIdx.z;
    const int tx = threadIdx.x, ty = threadIdx.y;
    const float* xb = x + (size_t)b * CC * TT;
#pragma unroll
    for (int q = 0; q < 4; q++)
        s[ty + 8*q][tx] = xb[(size_t)(c0 + ty + 8*q) * TT + t0 + tx];
    __syncthreads();
#pragma unroll
    for (int q = 0; q < 4; q++) {
        int t = t0 + ty + 8*q, c = c0 + tx;
        float v = s[tx][ty + 8*q];
        __nv_bfloat16 h = __float2bfloat16(v);
        float lo = v - __bfloat162float(h);
        size_t o = ((size_t)b * TT + t) * 512 + c;
        g_xT[o]       = h;
        g_xT[o + 256] = __float2bfloat16(lo);
    }
}

// ===========================================================================
// 1) squared norms  sq[b,t] = sum_c x[b,c,t]^2
// ===========================================================================
__global__ __launch_bounds__(256) void k_sq(const float* __restrict__ x)
{
    int n = blockIdx.x * 256 + threadIdx.x;
    int b = n >> 11;
    int t = n & (TT - 1);
    const float* p = x + (size_t)b * CC * TT + t;
    float s = 0.f;
#pragma unroll 8
    for (int c = 0; c < CC; c++) {
        float v = p[(size_t)c * TT];
        s += v * v;
    }
    g_sq[n] = s;
}

// ===========================================================================
// 2) FUSED gram + dual top-k via legacy mma.sync (bf16 hi/lo 3-pass, K=256)
//    gram = Ahi*Bhi + Ahi*Blo + Alo*Bhi   (lo*lo dropped, ~2^-18 relative)
//    CTA: 128 i-rows, 8 warps (4M x 2N, each warp 32x32), 32 j-tiles of 64.
// ===========================================================================
#define OFF_SQJ  0                  // 64 floats
#define OFF_A    1024               // 128 x 512 bf16 = 131072 B (swizzled)
#define OFF_B    (OFF_A + 131072)   // 64 x 512 bf16 = 65536 B
#define OFF_DIST (OFF_B + 65536)    // 64 x 132 floats = 33792 B (dist[j][i])
#define GT_SMEM  (OFF_DIST + 33792) // 231424 B

#define DPAD 132

__device__ __forceinline__ void ins10(float v, int j, float* lv, int* li)
{
    if (v < lv[9] || (v == lv[9] && j < li[9])) {
        lv[9] = v; li[9] = j;
#pragma unroll
        for (int q = 9; q > 0; q--) {
            bool sw = (lv[q] < lv[q-1]) || (lv[q] == lv[q-1] && li[q] < li[q-1]);
            if (sw) {
                float tv = lv[q]; lv[q] = lv[q-1]; lv[q-1] = tv;
                int   ti = li[q]; li[q] = li[q-1]; li[q-1] = ti;
            }
        }
    }
}

__device__ __forceinline__ void ldm_x4(uint32_t& r0, uint32_t& r1,
                                       uint32_t& r2, uint32_t& r3, uint32_t addr)
{
    asm volatile("ldmatrix.sync.aligned.m8n8.x4.shared.b16 {%0,%1,%2,%3}, [%4];"
                 : "=r"(r0), "=r"(r1), "=r"(r2), "=r"(r3) : "r"(addr));
}

__device__ __forceinline__ void mma_bf16(float* d, uint32_t a0, uint32_t a1,
                                         uint32_t a2, uint32_t a3,
                                         uint32_t b0, uint32_t b1)
{
    asm volatile("mma.sync.aligned.m16n8k16.row.col.f32.bf16.bf16.f32 "
                 "{%0,%1,%2,%3}, {%4,%5,%6,%7}, {%8,%9}, {%0,%1,%2,%3};"
                 : "+f"(d[0]), "+f"(d[1]), "+f"(d[2]), "+f"(d[3])
                 : "r"(a0), "r"(a1), "r"(a2), "r"(a3), "r"(b0), "r"(b1));
}

__global__ void __launch_bounds__(256, 1) k_gramtopk(const int* __restrict__ num_frms)
{
    extern __shared__ char smem[];
    const uint32_t sb = smem_u32(smem);
    float* s_sqj  = (float*)(smem + OFF_SQJ);
    float* s_dist = (float*)(smem + OFF_DIST);

    const int tid  = threadIdx.x;
    const int lane = tid & 31;
    const int w    = tid >> 5;
    const int wm   = w >> 1;            // 0..3 -> rows wm*32
    const int wn   = w & 1;             // 0..1 -> cols wn*32
    const int i0   = blockIdx.x * 128;
    const int b    = blockIdx.y;

    const __nv_bfloat16* gx = g_xT + (size_t)b * TT * 512;

    // ---- load A tile (128 rows x 512 bf16), swizzled 16B chunks ----
#pragma unroll
    for (int q = 0; q < 32; q++) {
        int id = tid + q * 256;                     // 0..8191
        int r  = id >> 6, c16 = id & 63;
        uint4 v = *(const uint4*)(gx + (size_t)(i0 + r) * 512 + c16 * 8);
        *(uint4*)(smem + OFF_A + r * 1024 + ((c16 ^ (r & 7)) << 4)) = v;
    }

    // ---- per-thread topk setup (thread t: row t&127, col-half t>>7) ----
    const int rowi = tid & 127;
    const int half = tid >> 7;
    const int nf   = num_frms[b];
    const int thr  = nf + 20;
    const bool condb = (nf <= 819);
    const int i    = i0 + rowi;
    const bool irow = (i >= thr);
    const float sqi = g_sq[b * TT + i];

    float ov[10]; int oi[10];
    float av[10]; int ai[10];
#pragma unroll
    for (int q = 0; q < 10; q++) {
        ov[q] = CUDART_INF_F; oi[q] = 0x7fffffff;
        av[q] = CUDART_INF_F; ai[q] = 0x7fffffff;
    }

    // ---- precomputed per-lane ldmatrix address components ----
    const int aRow  = (lane & 15);
    const int aDel  = lane >> 4;
    const uint32_t aBase0 = sb + OFF_A + (uint32_t)(wm*32 +  0 + aRow) * 1024;
    const uint32_t aBase1 = sb + OFF_A + (uint32_t)(wm*32 + 16 + aRow) * 1024;
    const int aXor = aRow & 7;
    const int bRowL = (lane & 7) | ((lane & 16) >> 1);   // 0..15
    const int bDel  = (lane >> 3) & 1;
    const uint32_t bBase0 = sb + OFF_B + (uint32_t)(wn*32 +  0 + bRowL) * 1024;
    const uint32_t bBase1 = sb + OFF_B + (uint32_t)(wn*32 + 16 + bRowL) * 1024;
    const int bXor = lane & 7;

    // ---- main loop over 32 j-tiles of 64 ----
    for (int jt = 0; jt < 32; jt++) {
        const int j0 = jt * 64;
        __syncthreads();                 // prev dist consumed; B reusable
        // load B tile (64 rows x 512 bf16), swizzled
#pragma unroll
        for (int q = 0; q < 16; q++) {
            int id = tid + q * 256;                 // 0..4095
            int r  = id >> 6, c16 = id & 63;
            uint4 v = *(const uint4*)(gx + (size_t)(j0 + r) * 512 + c16 * 8);
            *(uint4*)(smem + OFF_B + r * 1024 + ((c16 ^ (r & 7)) << 4)) = v;
        }
        if (tid < 64) s_sqj[tid] = g_sq[b * TT + j0 + tid];
        __syncthreads();

        float acc[2][4][4];
#pragma unroll
        for (int mi = 0; mi < 2; mi++)
#pragma unroll
            for (int ni = 0; ni < 4; ni++)
#pragma unroll
                for (int e = 0; e < 4; e++) acc[mi][ni][e] = 0.f;

        // 16 k-steps; chunks 0..31 = hi, 32..63 = lo
#pragma unroll 2
        for (int s = 0; s < 16; s++) {
            uint32_t ah[2][4], al[2][4], bh[4][2], bl[4][2];
            const int ca = 2*s + aDel;
            const uint32_t aoh = (uint32_t)((ca        ^ aXor) << 4);
            const uint32_t aol = (uint32_t)(((ca + 32) ^ aXor) << 4);
            ldm_x4(ah[0][0], ah[0][1], ah[0][2], ah[0][3], aBase0 + aoh);
            ldm_x4(ah[1][0], ah[1][1], ah[1][2], ah[1][3], aBase1 + aoh);
            ldm_x4(al[0][0], al[0][1], al[0][2], al[0][3], aBase0 + aol);
            ldm_x4(al[1][0], al[1][1], al[1][2], al[1][3], aBase1 + aol);
            const int cb = 2*s + bDel;
            const uint32_t boh = (uint32_t)((cb        ^ bXor) << 4);
            const uint32_t bol = (uint32_t)(((cb + 32) ^ bXor) << 4);
            ldm_x4(bh[0][0], bh[0][1], bh[1][0], bh[1][1], bBase0 + boh);
            ldm_x4(bh[2][0], bh[2][1], bh[3][0], bh[3][1], bBase1 + boh);
            ldm_x4(bl[0][0], bl[0][1], bl[1][0], bl[1][1], bBase0 + bol);
            ldm_x4(bl[2][0], bl[2][1], bl[3][0], bl[3][1], bBase1 + bol);
#pragma unroll
            for (int mi = 0; mi < 2; mi++)
#pragma unroll
                for (int ni = 0; ni < 4; ni++) {
                    mma_bf16(acc[mi][ni], ah[mi][0], ah[mi][1], ah[mi][2], ah[mi][3],
                             bh[ni][0], bh[ni][1]);
                    mma_bf16(acc[mi][ni], ah[mi][0], ah[mi][1], ah[mi][2], ah[mi][3],
                             bl[ni][0], bl[ni][1]);
                    mma_bf16(acc[mi][ni], al[mi][0], al[mi][1], al[mi][2], al[mi][3],
                             bh[ni][0], bh[ni][1]);
                }
        }

        __syncthreads();                 // dist region free (scanned last iter)
        // epilogue: write transposed dist[j][i] (raw gram values)
        {
            const int rB = wm*32 + (lane >> 2);
            const int cB = wn*32 + 2*(lane & 3);
#pragma unroll
            for (int mi = 0; mi < 2; mi++) {
                int r0 = rB + mi*16;
#pragma unroll
                for (int ni = 0; ni < 4; ni++) {
                    int c0 = cB + ni*8;
                    s_dist[(c0    ) * DPAD + r0    ] = acc[mi][ni][0];
                    s_dist[(c0 + 1) * DPAD + r0    ] = acc[mi][ni][1];
                    s_dist[(c0    ) * DPAD + r0 + 8] = acc[mi][ni][2];
                    s_dist[(c0 + 1) * DPAD + r0 + 8] = acc[mi][ni][3];
                }
            }
        }
        __syncthreads();

        // scan: thread handles its half-row (32 cols)
#pragma unroll 8
        for (int c = 0; c < 32; c++) {
            int cc = half * 32 + c;
            float g = s_dist[cc * DPAD + rowi];
            float v = sqi + s_sqj[cc] - 2.f * g;
            int jn = j0 + cc;
            ins10(v, jn, ov, oi);
            if (!(irow && jn >= thr)) ins10(v, jn, av, ai);
        }
    }

    // ---- merge halves: threads 128..255 publish, threads 0..127 absorb ----
    __syncthreads();
    int* mrg = (int*)(smem + OFF_DIST);
    if (half == 1) {
        int base = rowi * 40;
#pragma unroll
        for (int q = 0; q < 10; q++) {
            mrg[base +      q] = __float_as_int(ov[q]);
            mrg[base + 10 + q] = oi[q];
            mrg[base + 20 + q] = __float_as_int(av[q]);
            mrg[base + 30 + q] = ai[q];
        }
    }
    __syncthreads();
    if (half == 0) {
        int base = rowi * 40;
#pragma unroll
        for (int q = 0; q < 10; q++)
            ins10(__int_as_float(mrg[base + q]), mrg[base + 10 + q], ov, oi);
#pragma unroll
        for (int q = 0; q < 10; q++)
            ins10(__int_as_float(mrg[base + 20 + q]), mrg[base + 30 + q], av, ai);

        int outI[10];
#pragma unroll
        for (int q = 0; q < 5; q++) outI[q] = oi[q];
        if (condb) {
            int cnt = 5;
#pragma unroll
            for (int q = 0; q < 10; q++) {
                int c = ai[q];
                bool dup = (c == outI[0]) | (c == outI[1]) | (c == outI[2]) |
                           (c == outI[3]) | (c == outI[4]);
                if (!dup && cnt < 10) { outI[cnt] = c; cnt++; }
            }
        } else {
#pragma unroll
            for (int q = 5; q < 10; q++) outI[q] = oi[q];
        }
        int row = b * TT + i;
#pragma unroll
        for (int k = 0; k < KNN; k++)
            g_neigh[(size_t)row * KNN + k] = b * TT + outI[k];
    }
}

// ===========================================================================
// 4) Y1 = W1 * feat, Y2 = W2 * feat
// ===========================================================================
__global__ __launch_bounds__(256) void k_mlp(const float* __restrict__ x,
                                             const float* __restrict__ Wm)
{
    __shared__ float xs[16][64];
    __shared__ float w1s[16][128];
    __shared__ float w2s[16][128];

    const int b  = blockIdx.z;
    const int t0 = blockIdx.x * 64;
    const int o0 = blockIdx.y * 128;
    const int tid = threadIdx.x;
    const int tx = tid & 15;
    const int ty = tid >> 4;
    const float* xb = x + (size_t)b * CC * TT;

    float a1[4][8], a2[4][8];
#pragma unroll
    for (int ti = 0; ti < 4; ti++)
#pragma unroll
        for (int oi = 0; oi < 8; oi++) { a1[ti][oi] = 0.f; a2[ti][oi] = 0.f; }

    for (int kt = 0; kt < CC; kt += 16) {
        float4 xv = *(const float4*)(xb + (size_t)(kt + (tid >> 4)) * TT + t0 + (tid & 15) * 4);
        int lin0 = tid, lin1 = tid + 256;
        int ol0 = lin0 & 127, kg0 = lin0 >> 7;
        int ol1 = lin1 & 127, kg1 = lin1 >> 7;
        float4 w1v0 = *(const float4*)(Wm + (size_t)(o0 + ol0) * 512 + kt + kg0 * 4);
        float4 w2v0 = *(const float4*)(Wm + (size_t)(o0 + ol0) * 512 + 256 + kt + kg0 * 4);
        float4 w1v1 = *(const float4*)(Wm + (size_t)(o0 + ol1) * 512 + kt + kg1 * 4);
        float4 w2v1 = *(const float4*)(Wm + (size_t)(o0 + ol1) * 512 + 256 + kt + kg1 * 4);
        __syncthreads();
        *(float4*)&xs[tid >> 4][(tid & 15) * 4] = xv;
        {
            int kk = kg0 * 4;
            w1s[kk][ol0]=w1v0.x; w1s[kk+1][ol0]=w1v0.y; w1s[kk+2][ol0]=w1v0.z; w1s[kk+3][ol0]=w1v0.w;
            w2s[kk][ol0]=w2v0.x; w2s[kk+1][ol0]=w2v0.y; w2s[kk+2][ol0]=w2v0.z; w2s[kk+3][ol0]=w2v0.w;
        }
        {
            int kk = kg1 * 4;
            w1s[kk][ol1]=w1v1.x; w1s[kk+1][ol1]=w1v1.y; w1s[kk+2][ol1]=w1v1.z; w1s[kk+3][ol1]=w1v1.w;
            w2s[kk][ol1]=w2v1.x; w2s[kk+1][ol1]=w2v1.y; w2s[kk+2][ol1]=w2v1.z; w2s[kk+3][ol1]=w2v1.w;
        }
        __syncthreads();
#pragma unroll
        for (int kk = 0; kk < 16; kk++) {
            float xr[4];
            *(float4*)xr = *(float4*)&xs[kk][4*ty];
            float w1r[8], w2r[8];
            *(float4*)&w1r[0] = *(float4*)&w1s[kk][4*tx];
            *(float4*)&w1r[4] = *(float4*)&w1s[kk][64 + 4*tx];
            *(float4*)&w2r[0] = *(float4*)&w2s[kk][4*tx];
            *(float4*)&w2r[4] = *(float4*)&w2s[kk][64 + 4*tx];
#pragma unroll
            for (int ti = 0; ti < 4; ti++)
#pragma unroll
                for (int oi = 0; oi < 8; oi++) {
                    a1[ti][oi] += xr[ti] * w1r[oi];
                    a2[ti][oi] += xr[ti] * w2r[oi];
                }
        }
    }

#pragma unroll
    for (int ti = 0; ti < 4; ti++) {
        size_t base = (size_t)(b*TT + t0 + 4*ty + ti) * CC + o0;
        *(float4*)(g_Y1 + base + 4*tx)      = make_float4(a1[ti][0], a1[ti][1], a1[ti][2], a1[ti][3]);
        *(float4*)(g_Y1 + base + 64 + 4*tx) = make_float4(a1[ti][4], a1[ti][5], a1[ti][6], a1[ti][7]);
        *(float4*)(g_Y2 + base + 4*tx)      = make_float4(a2[ti][0], a2[ti][1], a2[ti][2], a2[ti][3]);
        *(float4*)(g_Y2 + base + 64 + 4*tx) = make_float4(a2[ti][4], a2[ti][5], a2[ti][6], a2[ti][7]);
    }
}

// ===========================================================================
// 5) conv1d (k=3, pad 1); writes S = conv + b_conv + b_mlp
// ===========================================================================
__global__ __launch_bounds__(256) void k_conv(const float* __restrict__ x,
                                              const float* __restrict__ Wc,
                                              const float* __restrict__ bc,
                                              const float* __restrict__ bm)
{
    __shared__ float xs[16][68];
    __shared__ float wcs[3][16][128];

    const int b  = blockIdx.z;
    const int t0 = blockIdx.x * 64;
    const int o0 = blockIdx.y * 128;
    const int tid = threadIdx.x;
    const int tx = tid & 15;
    const int ty = tid >> 4;
    const float* xb = x + (size_t)b * CC * TT;

    float ac[4][8];
#pragma unroll
    for (int ti = 0; ti < 4; ti++)
#pragma unroll
        for (int oi = 0; oi < 8; oi++) ac[ti][oi] = 0.f;

    for (int kt = 0; kt < CC; kt += 16) {
        __syncthreads();
        for (int idx = tid; idx < 16 * 66; idx += 256) {
            int kk = idx / 66, u = idx - kk * 66;
            int gt = t0 - 1 + u;
            float v = (gt >= 0 && gt < TT) ? xb[(size_t)(kt + kk) * TT + gt] : 0.f;
            xs[kk][u] = v;
        }
        for (int idx = tid; idx < 3 * 16 * 128; idx += 256) {
            int ol = idx & 127;
            int kk = (idx >> 7) & 15;
            int s  = idx >> 11;
            wcs[s][kk][ol] = Wc[(size_t)(o0 + ol) * 768 + (kt + kk) * 3 + s];
        }
        __syncthreads();
#pragma unroll
        for (int kk = 0; kk < 16; kk++) {
            float xr[6];
#pragma unroll
            for (int u = 0; u < 6; u++) xr[u] = xs[kk][4*ty + u];
#pragma unroll
            for (int s = 0; s < 3; s++) {
                float wv[8];
                *(float4*)&wv[0] = *(float4*)&wcs[s][kk][4*tx];
                *(float4*)&wv[4] = *(float4*)&wcs[s][kk][64 + 4*tx];
#pragma unroll
                for (int ti = 0; ti < 4; ti++)
#pragma unroll
                    for (int oi = 0; oi < 8; oi++)
                        ac[ti][oi] += xr[ti + s] * wv[oi];
            }
        }
    }

    float bias[8];
#pragma unroll
    for (int oi = 0; oi < 8; oi++) {
        int o = o0 + ((oi < 4) ? (4*tx + oi) : (64 + 4*tx + oi - 4));
        bias[oi] = bc[o] + bm[o];
    }
#pragma unroll
    for (int ti = 0; ti < 4; ti++) {
        size_t base = (size_t)(b*TT + t0 + 4*ty + ti) * CC + o0;
        *(float4*)(g_S + base + 4*tx)      = make_float4(ac[ti][0]+bias[0], ac[ti][1]+bias[1],
                                                         ac[ti][2]+bias[2], ac[ti][3]+bias[3]);
        *(float4*)(g_S + base + 64 + 4*tx) = make_float4(ac[ti][4]+bias[4], ac[ti][5]+bias[5],
                                                         ac[ti][6]+bias[6], ac[ti][7]+bias[7]);
    }
}

// ===========================================================================
// 6) final: out = relu(maxpool2(S + Y2 + max_k Y1[nbr]))
// ===========================================================================
__global__ __launch_bounds__(256) void k_final(float* __restrict__ out)
{
    __shared__ float rt[256][33];
    __shared__ int   nb[80];

    const int gx = blockIdx.x;
    const int b  = blockIdx.y;
    const int tid = threadIdx.x;
    const int t2base = gx * 32;

    for (int sub = 0; sub < 8; sub++) {
        __syncthreads();
        int nbase = b * TT + (t2base + sub * 4) * 2;
        if (tid < 80) nb[tid] = g_neigh[(size_t)nbase * KNN + tid];
        __syncthreads();
        int o = tid;
#pragma unroll
        for (int t2l = 0; t2l < 4; t2l++) {
            int p0 = t2l * 2, p1 = p0 + 1;
            float m0 = -CUDART_INF_F, m1 = -CUDART_INF_F;
#pragma unroll
            for (int k = 0; k < KNN; k++) {
                m0 = fmaxf(m0, g_Y1[(size_t)nb[p0*KNN + k] * CC + o]);
                m1 = fmaxf(m1, g_Y1[(size_t)nb[p1*KNN + k] * CC + o]);
            }
            int n0 = nbase + p0, n1 = nbase + p1;
            float v0 = g_S[(size_t)n0*CC + o] + g_Y2[(size_t)n0*CC + o] + m0;
            float v1 = g_S[(size_t)n1*CC + o] + g_Y2[(size_t)n1*CC + o] + m1;
            rt[o][sub*4 + t2l] = fmaxf(fmaxf(v0, v1), 0.f);
        }
    }
    __syncthreads();
    float* ob = out + (size_t)b * CC * (TT/2) + t2base;
    for (int w = 0; w < 32; w++) {
        int lin = w * 256 + tid;
        int o = lin >> 5, c = lin & 31;
        ob[(size_t)o * (TT/2) + c] = rt[o][c];
    }
}

// ===========================================================================
extern "C" void kernel_launch(void* const* d_in, const int* in_sizes, int n_in,
                              void* d_out, int out_size)
{
    const float* x   = (const float*)d_in[0];
    const int*   nfr = (const int*)  d_in[1];
    const float* Wc  = (const float*)d_in[2];
    const float* bc  = (const float*)d_in[3];
    const float* Wm  = (const float*)d_in[4];
    const float* bm  = (const float*)d_in[5];
    float* out = (float*)d_out;

    cudaFuncSetAttribute(k_gramtopk, cudaFuncAttributeMaxDynamicSharedMemorySize, GT_SMEM);

    k_cvt <<<dim3(64, 8, BB), dim3(32, 8)>>>(x);
    k_sq  <<<NN/256, 256>>>(x);
    k_gramtopk<<<dim3(16, BB), 256, GT_SMEM>>>(nfr);
    k_mlp <<<dim3(32, 2, BB), 256>>>(x, Wm);
    k_conv<<<dim3(32, 2, BB), 256>>>(x, Wc, bc, bm);
    k_final<<<dim3(32, BB), 256>>>(out);
}